// round 14
// baseline (speedup 1.0000x reference)
#include <cuda_runtime.h>
#include <cuda_fp16.h>
#include <cstdint>

// Problem constants
#define MM      16
#define NN      8192
#define KK      8192
#define GROUPK  128
#define SPLITK  16
#define CHUNK   512         // K per split = KK/SPLITK
#define NSTEPS  (KK / 16)   // 512 k16 steps
#define WSTEPS  (CHUNK / 16) // 32 k16 steps per warp

// Static device scratch (no allocation allowed)
__device__ uint4  g_xfrag[NSTEPS * 32];            // 256 KB A fragments (fp16x2 x4)
__device__ float  g_scalesf[(KK / GROUPK) * NN];   // 2 MB scales (only if src 16-bit)
__device__ int    g_dtype;                         // 0=fp16, 1=bf16, 2=fp32

__device__ __forceinline__ float load_as_float(const void* p, int i, int dt)
{
    if (dt == 2) return ((const float*)p)[i];
    if (dt == 1) {
        const unsigned short b = ((const unsigned short*)p)[i];
        return __uint_as_float(((unsigned)b) << 16);
    }
    return __half2float(((const __half*)p)[i]);
}

// ---------------------------------------------------------------------------
// Prep kernel (one launch): classify dtype, build A fragments, out = bias,
// convert scales only if 16-bit source.
// ---------------------------------------------------------------------------
__global__ __launch_bounds__(256) void prep_kernel(
    const void* __restrict__ x, const void* __restrict__ sc,
    const void* __restrict__ bi, float* __restrict__ out)
{
    __shared__ int s_dt;
    if (threadIdx.x < 32) {
        const unsigned lane = threadIdx.x;
        const unsigned w0 = ((const unsigned*)x)[lane];
        const unsigned w1 = ((const unsigned*)x)[32 + lane];

        auto wordtest = [](unsigned w) -> bool {
            const int e_lo = (w >> 7)  & 0xFF;
            const int e_hi = (w >> 23) & 0xFF;
            return e_lo >= 100 && e_lo <= 135 && e_hi >= 100 && e_hi <= 135;
        };
        const int lofl = __popc(__ballot_sync(0xffffffffu, wordtest(w0)))
                       + __popc(__ballot_sync(0xffffffffu, wordtest(w1)));

        int sm = 0;
        if (((w0 >> 10) & 0x1F) <= 12) ++sm;
        if (((w0 >> 26) & 0x1F) <= 12) ++sm;
        if (((w1 >> 10) & 0x1F) <= 12) ++sm;
        if (((w1 >> 26) & 0x1F) <= 12) ++sm;
        const int small = __reduce_add_sync(0xffffffffu, sm);

        if (lane == 0) {
            int dt;
            if (lofl < 27)        dt = 2;   // fp32
            else if (small >= 8)  dt = 0;   // fp16
            else                  dt = 1;   // bf16
            s_dt = dt;
            if (blockIdx.x == 0) g_dtype = dt;
        }
    }
    __syncthreads();
    const int dt = s_dt;

    const int tid = blockIdx.x * blockDim.x + threadIdx.x;   // 0..32767

    // ---- A fragments: 512 steps * 32 lanes = 16384 threads ----
    if (tid < NSTEPS * 32) {
        const int t    = tid >> 5;
        const int lane = tid & 31;
        const int lr   = lane >> 2;
        const int lc   = lane & 3;
        const int kb   = t * 16;

        const int r0 = lr * KK, r1 = (lr + 8) * KK;
        const int ka = kb + 2 * lc;       // low k-pair (even)
        const int kc = kb + 8 + 2 * lc;   // high k-pair (even)

        __half2 h0, h1, h2, h3;
        if (dt == 2) {
            const float2* x2 = (const float2*)x;
            const float2 p0 = x2[(r0 + ka) >> 1];
            const float2 p1 = x2[(r1 + ka) >> 1];
            const float2 p2 = x2[(r0 + kc) >> 1];
            const float2 p3 = x2[(r1 + kc) >> 1];
            h0 = __floats2half2_rn(p0.x, p0.y);
            h1 = __floats2half2_rn(p1.x, p1.y);
            h2 = __floats2half2_rn(p2.x, p2.y);
            h3 = __floats2half2_rn(p3.x, p3.y);
        } else {
            h0 = __floats2half2_rn(load_as_float(x, r0 + ka, dt),
                                   load_as_float(x, r0 + ka + 1, dt));
            h1 = __floats2half2_rn(load_as_float(x, r1 + ka, dt),
                                   load_as_float(x, r1 + ka + 1, dt));
            h2 = __floats2half2_rn(load_as_float(x, r0 + kc, dt),
                                   load_as_float(x, r0 + kc + 1, dt));
            h3 = __floats2half2_rn(load_as_float(x, r1 + kc, dt),
                                   load_as_float(x, r1 + kc + 1, dt));
        }
        uint4 v;
        v.x = *reinterpret_cast<unsigned*>(&h0);
        v.y = *reinterpret_cast<unsigned*>(&h1);
        v.z = *reinterpret_cast<unsigned*>(&h2);
        v.w = *reinterpret_cast<unsigned*>(&h3);
        g_xfrag[tid] = v;
    }

    // ---- out = bias : 32768 threads x float4 = 131072 elements ----
    {
        const int idx = tid * 4;
        const int n   = idx & (NN - 1);
        float4 b4;
        if (dt == 2) {
            b4 = *reinterpret_cast<const float4*>(&((const float*)bi)[n]);
        } else {
            b4 = make_float4(load_as_float(bi, n, dt),
                             load_as_float(bi, n + 1, dt),
                             load_as_float(bi, n + 2, dt),
                             load_as_float(bi, n + 3, dt));
        }
        *reinterpret_cast<float4*>(&out[idx]) = b4;
    }

    // ---- scales conversion only when source is 16-bit ----
    if (dt != 2) {
        const int stride = gridDim.x * blockDim.x;
        for (int i = tid; i < (KK / GROUPK) * NN; i += stride)
            g_scalesf[i] = load_as_float(sc, i, dt);
    }
}

// ---------------------------------------------------------------------------
// GEMM: each warp computes a 16 x 32 output tile over one K-chunk and
// accumulates directly into out via vectorized fp32 atomic reductions.
// Software-pipelined mainloop: q-words + A-fragment double-buffered one
// k16-step ahead (16 independent loads in flight per warp).
// ---------------------------------------------------------------------------
__global__ __launch_bounds__(128) void quant_gemm_kernel(
    const unsigned* __restrict__ qw,     // [KK/8, NN] packed int4
    const float* __restrict__ sc_src,    // scales source if fp32
    float* __restrict__ out)
{
    const int lane = threadIdx.x & 31;
    const int warp = threadIdx.x >> 5;
    const int lr   = lane >> 2;   // mma column within n8 tile / A row
    const int lc   = lane & 3;    // k-pair selector
    const int shft = lc * 8;      // byte select within packed word

    const int nb = blockIdx.x * 128 + warp * 32;   // warp's N base
    const int k0 = blockIdx.y * CHUNK;             // split's K base
    const int t0 = k0 >> 4;                        // first k16-step of split
    const int cbase = nb + lr;                     // this thread's column base

    const float* scp = (g_dtype == 2) ? sc_src : g_scalesf;

    const __half2 off1032 = __half2half2(__ushort_as_half(0x6408)); // 1032.0

    // Base pointer for this thread's q loads at step t0: row = 2*t, col cbase
    const unsigned* qp = qw + (size_t)(t0 * 2) * NN + cbase;
    const uint4*    fp = g_xfrag + (size_t)t0 * 32 + lane;

    float acc[16];
    #pragma unroll
    for (int i = 0; i < 16; ++i) acc[i] = 0.f;
    float grp[16];
    #pragma unroll
    for (int i = 0; i < 16; ++i) grp[i] = 0.f;

    // Double buffers
    unsigned q0[2][4], q1[2][4];
    uint4 av[2];

    // Prologue: load step 0 into buffer 0
    #pragma unroll
    for (int i = 0; i < 4; ++i) {
        q0[0][i] = __ldg(qp + 8 * i);
        q1[0][i] = __ldg(qp + NN + 8 * i);
    }
    av[0] = *fp;

    #pragma unroll
    for (int t = 0; t < WSTEPS; ++t) {
        const int cur = t & 1;
        const int nxt = cur ^ 1;

        // Prefetch step t+1 (independent of current compute)
        if (t + 1 < WSTEPS) {
            const unsigned* qn = qp + (size_t)(t + 1) * 2 * NN;
            #pragma unroll
            for (int i = 0; i < 4; ++i) {
                q0[nxt][i] = __ldg(qn + 8 * i);
                q1[nxt][i] = __ldg(qn + NN + 8 * i);
            }
            av[nxt] = fp[(t + 1) * 32];
        }

        // Compute step t
        #pragma unroll
        for (int i = 0; i < 4; ++i) {        // 4 x n8 tiles -> 32 columns
            const unsigned t0w = q0[cur][i] >> shft;
            const unsigned t1w = q1[cur][i] >> shft;

            // two nibbles -> fp16x2 {1024+lo,1024+hi}; -1032 -> (nib-8)
            unsigned h0 = (t0w & 0xFu) | ((t0w << 12) & 0xF0000u) | 0x64006400u;
            unsigned h1 = (t1w & 0xFu) | ((t1w << 12) & 0xF0000u) | 0x64006400u;
            __half2 bh0 = __hsub2(*reinterpret_cast<__half2*>(&h0), off1032);
            __half2 bh1 = __hsub2(*reinterpret_cast<__half2*>(&h1), off1032);
            const unsigned b0 = *reinterpret_cast<unsigned*>(&bh0);
            const unsigned b1 = *reinterpret_cast<unsigned*>(&bh1);

            asm volatile(
                "mma.sync.aligned.m16n8k16.row.col.f32.f16.f16.f32 "
                "{%0,%1,%2,%3}, {%4,%5,%6,%7}, {%8,%9}, {%0,%1,%2,%3};\n"
                : "+f"(grp[4 * i + 0]), "+f"(grp[4 * i + 1]),
                  "+f"(grp[4 * i + 2]), "+f"(grp[4 * i + 3])
                : "r"(av[cur].x), "r"(av[cur].y), "r"(av[cur].z), "r"(av[cur].w),
                  "r"(b0), "r"(b1));
        }

        // Group boundary: apply per-group scales into acc, reset grp
        if ((t & 7) == 7) {
            const int gg = (k0 >> 7) + (t >> 3);
            #pragma unroll
            for (int i = 0; i < 4; ++i) {
                const int cb = nb + 8 * i + lc * 2;
                const float2 sf = *reinterpret_cast<const float2*>(
                    &scp[(size_t)gg * NN + cb]);
                acc[4 * i + 0] += grp[4 * i + 0] * sf.x;
                acc[4 * i + 1] += grp[4 * i + 1] * sf.y;
                acc[4 * i + 2] += grp[4 * i + 2] * sf.x;
                acc[4 * i + 3] += grp[4 * i + 3] * sf.y;
                grp[4 * i + 0] = 0.f;
                grp[4 * i + 1] = 0.f;
                grp[4 * i + 2] = 0.f;
                grp[4 * i + 3] = 0.f;
            }
        }
    }

    // Accumulate directly into out (bias pre-loaded by prep_kernel).
    #pragma unroll
    for (int i = 0; i < 4; ++i) {
        const int cb = nb + 8 * i + lc * 2;
        float* p0 = &out[lr * NN + cb];
        float* p1 = &out[(lr + 8) * NN + cb];
        asm volatile("red.global.add.v2.f32 [%0], {%1, %2};"
                     :: "l"(p0), "f"(acc[4 * i + 0]), "f"(acc[4 * i + 1])
                     : "memory");
        asm volatile("red.global.add.v2.f32 [%0], {%1, %2};"
                     :: "l"(p1), "f"(acc[4 * i + 2]), "f"(acc[4 * i + 3])
                     : "memory");
    }
}

extern "C" void kernel_launch(void* const* d_in, const int* in_sizes, int n_in,
                              void* d_out, int out_size)
{
    // Bind inputs by UNIQUE element counts (order-proof):
    //   x: 131072, qweight: 8388608, scales: 524288, bias: 8192
    const void*     x      = nullptr;
    const unsigned* qw     = nullptr;
    const void*     scales = nullptr;
    const void*     bias   = nullptr;

    for (int i = 0; i < n_in; ++i) {
        switch (in_sizes[i]) {
            case MM * KK:            x      = d_in[i];                  break;
            case (KK / 8) * NN:      qw     = (const unsigned*)d_in[i]; break;
            case (KK / GROUPK) * NN: scales = d_in[i];                  break;
            case NN:                 bias   = d_in[i];                  break;
            default: break;
        }
    }
    if (!x || !qw || !scales || !bias) {
        x      = d_in[0];
        qw     = (const unsigned*)d_in[1];
        scales = d_in[2];
        bias   = d_in[3];
    }

    float* out = (float*)d_out;

    prep_kernel<<<128, 256>>>(x, scales, bias, out);
    quant_gemm_kernel<<<dim3(NN / 128, SPLITK), 128>>>(qw, (const float*)scales, out);
}